// round 1
// baseline (speedup 1.0000x reference)
#include <cuda_runtime.h>
#include <cstdint>

#define HH 256
#define NN 64
#define LL 2048

// Scratch (no allocs allowed): dA (H,N,N) complex, dB (H,N) complex
__device__ float dAg[HH * NN * NN * 2];
__device__ float dBg[HH * NN * 2];

typedef unsigned long long u64;

__device__ __forceinline__ u64 fma2(u64 a, u64 b, u64 c) {
    u64 d;
    asm("fma.rn.f32x2 %0, %1, %2, %3;" : "=l"(d) : "l"(a), "l"(b), "l"(c));
    return d;
}
__device__ __forceinline__ u64 pack2(float lo, float hi) {
    u64 r;
    asm("mov.b64 %0, {%1, %2};" : "=l"(r) : "f"(lo), "f"(hi));
    return r;
}
__device__ __forceinline__ void unpack2(u64 v, float& lo, float& hi) {
    asm("mov.b64 {%0, %1}, %2;" : "=f"(lo), "=f"(hi) : "l"(v));
}

// ---------------------------------------------------------------------------
// Kernel 1: per-head bilinear transform.
//   A_back = I - dt/2 * Ac   (strictly diagonally dominant -> no pivoting)
//   Gauss-Jordan:  [A_back | A_fwd  B]  ->  [I | dA  dB/dt]
// One block per head, 256 threads.
// ---------------------------------------------------------------------------
__global__ void __launch_bounds__(256) setup_kernel(const float* __restrict__ A,
                                                    const float* __restrict__ B,
                                                    const float* __restrict__ logdt) {
    extern __shared__ float2 sm[];
    float2* Ab = sm;                       // [64][65]  (row pad 65 to break bank conflicts)
    float2* R  = sm + 64 * 65;             // [64][66]  cols 0..63 = A_fwd, col 64 = B
    float2* fc = sm + 64 * 65 + 64 * 66;   // [64] elimination factors
    __shared__ float2 pivs;
    __shared__ float dts;

    const int h = blockIdx.x;
    const int tid = threadIdx.x;

    if (tid == 0) dts = expf(logdt[h]);
    __syncthreads();
    const float dt = dts;
    const float hd = 0.5f * dt;

    const float* Ah = A + (size_t)h * NN * NN * 2;
    for (int idx = tid; idx < NN * NN; idx += 256) {
        int i = idx >> 6, j = idx & 63;
        float ar = Ah[idx * 2 + 0];
        float ai = Ah[idx * 2 + 1];
        float d = (i == j) ? 1.0f : 0.0f;
        Ab[i * 65 + j] = make_float2(d - hd * ar, -hd * ai);
        R[i * 66 + j]  = make_float2(d + hd * ar,  hd * ai);
    }
    if (tid < NN) {
        R[tid * 66 + 64] = make_float2(B[(h * NN + tid) * 2 + 0],
                                       B[(h * NN + tid) * 2 + 1]);
    }
    __syncthreads();

    for (int k = 0; k < NN; k++) {
        // phase A: stash column k factors, compute pivot reciprocal
        if (tid < NN) fc[tid] = Ab[tid * 65 + k];
        if (tid == 0) {
            float2 p = Ab[k * 65 + k];
            float inv = 1.0f / (p.x * p.x + p.y * p.y);
            pivs = make_float2(p.x * inv, -p.y * inv);
        }
        __syncthreads();
        // phase B: normalize row k (64 Ab cols + 65 R cols), zero fc[k]
        if (tid < 129) {
            float2 p = pivs;
            if (tid < 64) {
                float2 v = Ab[k * 65 + tid];
                Ab[k * 65 + tid] = make_float2(v.x * p.x - v.y * p.y,
                                               v.x * p.y + v.y * p.x);
            } else {
                int j = tid - 64;
                float2 v = R[k * 66 + j];
                R[k * 66 + j] = make_float2(v.x * p.x - v.y * p.y,
                                            v.x * p.y + v.y * p.x);
            }
        }
        if (tid == 255) fc[k] = make_float2(0.0f, 0.0f);
        __syncthreads();
        // phase C: eliminate column k everywhere (row k untouched: fc[k]=0)
        for (int idx = tid; idx < NN * NN; idx += 256) {
            int i = idx >> 6, j = idx & 63;
            float2 f = fc[i];
            float2 rk = Ab[k * 65 + j];
            float2 v = Ab[i * 65 + j];
            v.x -= f.x * rk.x - f.y * rk.y;
            v.y -= f.x * rk.y + f.y * rk.x;
            Ab[i * 65 + j] = v;
        }
        for (int idx = tid; idx < NN * 65; idx += 256) {
            int i = idx / 65, j = idx - i * 65;
            float2 f = fc[i];
            float2 rk = R[k * 66 + j];
            float2 v = R[i * 66 + j];
            v.x -= f.x * rk.x - f.y * rk.y;
            v.y -= f.x * rk.y + f.y * rk.x;
            R[i * 66 + j] = v;
        }
        __syncthreads();
    }

    // write dA, dB (dB scaled by dt)
    float2* dAo = ((float2*)dAg) + (size_t)h * NN * NN;
    for (int idx = tid; idx < NN * NN; idx += 256) {
        int i = idx >> 6, j = idx & 63;
        dAo[idx] = R[i * 66 + j];
    }
    if (tid < NN) {
        float2 b = R[tid * 66 + 64];
        ((float2*)dBg)[h * NN + tid] = make_float2(dt * b.x, dt * b.y);
    }
}

// ---------------------------------------------------------------------------
// Kernel 2: sequential scan  x <- dA x,  k[l] = Re(C . x).
// One block per head, 256 threads. dA lives in registers (loop-invariant):
// thread owns rows {n0,n0+1} x cols [8q, 8q+8). Complex MAC via fma.rn.f32x2:
//   acc(re,im) += xr*(ar,ai) + xi*(-ai,ar)
// x kept in smem as splats (xr,xr),(xi,xi); padded layout idx = 10*(m>>3)+(m&7)
// for conflict-free 8-address multicast reads and 16B-aligned vector loads.
// ---------------------------------------------------------------------------
__global__ void __launch_bounds__(256, 2) scan_kernel(const float* __restrict__ C,
                                                      float* __restrict__ out) {
    __shared__ __align__(16) u64 xbuf[2][2][80];  // [buf][re/im][padded 64]
    __shared__ float kpart[2][8];
    __shared__ float psum[64];

    const int h = blockIdx.x;
    const int tid = threadIdx.x;
    const int lane = tid & 31;
    const int warp = tid >> 5;
    const int q = lane & 7;         // m-slice: m in [8q, 8q+8)
    const int gl = lane >> 3;       // 0..3
    const int g = (warp << 2) | gl; // 0..31
    const int n0 = g * 2;           // = 8*warp + 2*gl

    // loop-invariant A pairs in registers
    const float2* Ah = ((const float2*)dAg) + (size_t)h * NN * NN;
    u64 a1[2][8], a2[2][8];
#pragma unroll
    for (int r = 0; r < 2; r++) {
        const float2* row = Ah + (n0 + r) * NN + q * 8;
#pragma unroll
        for (int j = 0; j < 8; j++) {
            float2 av = row[j];
            a1[r][j] = pack2(av.x, av.y);
            a2[r][j] = pack2(-av.y, av.x);
        }
    }
    const float2 c0 = ((const float2*)C)[h * NN + n0];
    const float2 c1 = ((const float2*)C)[h * NN + n0 + 1];

    // init x = dB (splat form), and k[0] = Re(C . dB)
    if (tid < NN) {
        float2 b = ((const float2*)dBg)[h * NN + tid];
        int ix = 10 * (tid >> 3) + (tid & 7);
        xbuf[0][0][ix] = pack2(b.x, b.x);
        xbuf[0][1][ix] = pack2(b.y, b.y);
        float2 cc = ((const float2*)C)[h * NN + tid];
        psum[tid] = cc.x * b.x - cc.y * b.y;
    }
    __syncthreads();

    float* outh = out + (size_t)h * LL;
    if (tid == 0) {
        float s = 0.0f;
#pragma unroll 8
        for (int i = 0; i < NN; i++) s += psum[i];
        outh[0] = s;
    }

    const int base = q * 10;
    const int ix0 = 10 * warp + 2 * gl;  // padded write index for n0

#pragma unroll 1
    for (int l = 1; l < LL; l++) {
        const int pb = (l - 1) & 1;
        const int nb = l & 1;
        const u64* XR = xbuf[pb][0];
        const u64* XI = xbuf[pb][1];
        u64 acc0 = 0, acc1 = 0;
#pragma unroll
        for (int j = 0; j < 8; j += 2) {
            ulonglong2 vr = *reinterpret_cast<const ulonglong2*>(XR + base + j);
            ulonglong2 vi = *reinterpret_cast<const ulonglong2*>(XI + base + j);
            acc0 = fma2(vr.x, a1[0][j], acc0);
            acc1 = fma2(vr.x, a1[1][j], acc1);
            acc0 = fma2(vi.x, a2[0][j], acc0);
            acc1 = fma2(vi.x, a2[1][j], acc1);
            acc0 = fma2(vr.y, a1[0][j + 1], acc0);
            acc1 = fma2(vr.y, a1[1][j + 1], acc1);
            acc0 = fma2(vi.y, a2[0][j + 1], acc0);
            acc1 = fma2(vi.y, a2[1][j + 1], acc1);
        }
        float r0, i0, r1, i1;
        unpack2(acc0, r0, i0);
        unpack2(acc1, r1, i1);
#pragma unroll
        for (int s = 1; s < 8; s <<= 1) {
            r0 += __shfl_xor_sync(0xffffffffu, r0, s);
            i0 += __shfl_xor_sync(0xffffffffu, i0, s);
            r1 += __shfl_xor_sync(0xffffffffu, r1, s);
            i1 += __shfl_xor_sync(0xffffffffu, i1, s);
        }
        if (q == 0) {  // owner lanes 0,8,16,24
            xbuf[nb][0][ix0]     = pack2(r0, r0);
            xbuf[nb][1][ix0]     = pack2(i0, i0);
            xbuf[nb][0][ix0 + 1] = pack2(r1, r1);
            xbuf[nb][1][ix0 + 1] = pack2(i1, i1);
            float kp = c0.x * r0 - c0.y * i0 + c1.x * r1 - c1.y * i1;
            kp += __shfl_xor_sync(0x01010101u, kp, 8);
            kp += __shfl_xor_sync(0x01010101u, kp, 16);
            if (lane == 0) kpart[nb][warp] = kp;
        }
        __syncthreads();
        if (tid == 0) {
            float s = kpart[nb][0] + kpart[nb][1] + kpart[nb][2] + kpart[nb][3]
                    + kpart[nb][4] + kpart[nb][5] + kpart[nb][6] + kpart[nb][7];
            outh[l] = s;
        }
    }
}

// ---------------------------------------------------------------------------

static const int SETUP_SMEM = (64 * 65 + 64 * 66 + 64) * (int)sizeof(float2);  // 67584

extern "C" void kernel_launch(void* const* d_in, const int* in_sizes, int n_in,
                              void* d_out, int out_size) {
    (void)in_sizes; (void)n_in; (void)out_size;
    const float* A     = (const float*)d_in[0];
    const float* B     = (const float*)d_in[1];
    const float* C     = (const float*)d_in[2];
    const float* logdt = (const float*)d_in[3];
    // d_in[4] = L (compile-time constant 2048 here)

    cudaFuncSetAttribute(setup_kernel, cudaFuncAttributeMaxDynamicSharedMemorySize,
                         SETUP_SMEM);
    setup_kernel<<<HH, 256, SETUP_SMEM>>>(A, B, logdt);
    scan_kernel<<<HH, 256>>>(C, (float*)d_out);
}

// round 2
// speedup vs baseline: 1.2570x; 1.2570x over previous
#include <cuda_runtime.h>
#include <cstdint>

#define HH 256
#define NN 64
#define LL 2048

// Scratch (no allocs allowed): dA (H,N,N) complex, dB (H,N) complex
__device__ float dAg[HH * NN * NN * 2];
__device__ float dBg[HH * NN * 2];

typedef unsigned long long u64;

__device__ __forceinline__ u64 fma2(u64 a, u64 b, u64 c) {
    u64 d;
    asm("fma.rn.f32x2 %0, %1, %2, %3;" : "=l"(d) : "l"(a), "l"(b), "l"(c));
    return d;
}
__device__ __forceinline__ u64 add2(u64 a, u64 b) {
    u64 d;
    asm("add.rn.f32x2 %0, %1, %2;" : "=l"(d) : "l"(a), "l"(b));
    return d;
}
__device__ __forceinline__ u64 pack2(float lo, float hi) {
    u64 r;
    asm("mov.b64 %0, {%1, %2};" : "=l"(r) : "f"(lo), "f"(hi));
    return r;
}
__device__ __forceinline__ void unpack2(u64 v, float& lo, float& hi) {
    asm("mov.b64 {%0, %1}, %2;" : "=f"(lo), "=f"(hi) : "l"(v));
}

// ---------------------------------------------------------------------------
// Kernel 1: per-head bilinear transform, 2 heads per block (128 thr/head).
//   A_back = I - dt/2 * Ac  (strictly diagonally dominant -> no pivoting)
//   In-place Gauss-Jordan inversion, then dA = 2*inv - I, dB = dt*(inv*Bc).
// ---------------------------------------------------------------------------
__global__ void __launch_bounds__(256) setup_kernel(const float* __restrict__ A,
                                                    const float* __restrict__ B,
                                                    const float* __restrict__ logdt) {
    extern __shared__ float2 sm[];  // 2 x [64][65]
    __shared__ float2 fc[2][64];
    __shared__ float2 bvec[2][64];
    __shared__ float2 pivs[2];
    __shared__ float dts[2];

    const int tid = threadIdx.x;
    const int hl = tid >> 7;
    const int t = tid & 127;
    const int h = blockIdx.x * 2 + hl;
    float2* M = sm + hl * (64 * 65);

    if (t == 0) dts[hl] = expf(logdt[h]);
    if (t < 64) bvec[hl][t] = make_float2(B[(h * NN + t) * 2 + 0],
                                          B[(h * NN + t) * 2 + 1]);
    __syncthreads();
    const float dt = dts[hl];
    const float hd = 0.5f * dt;

    const float* Ah = A + (size_t)h * NN * NN * 2;
    for (int idx = t; idx < NN * NN; idx += 128) {
        int i = idx >> 6, j = idx & 63;
        float ar = Ah[idx * 2 + 0];
        float ai = Ah[idx * 2 + 1];
        float d = (i == j) ? 1.0f : 0.0f;
        M[i * 65 + j] = make_float2(d - hd * ar, -hd * ai);
    }
    __syncthreads();

    for (int k = 0; k < NN; k++) {
        if (t < 64) fc[hl][t] = M[t * 65 + k];
        if (t == 0) {
            float2 p = M[k * 65 + k];
            float inv = 1.0f / (p.x * p.x + p.y * p.y);
            pivs[hl] = make_float2(p.x * inv, -p.y * inv);
        }
        __syncthreads();
        // row k: M[k][j] = M[k][j]/p (j!=k), M[k][k] = 1/p
        if (t < 64) {
            float2 p = pivs[hl];
            float2 v = (t == k) ? make_float2(1.0f, 0.0f) : M[k * 65 + t];
            M[k * 65 + t] = make_float2(v.x * p.x - v.y * p.y,
                                        v.x * p.y + v.y * p.x);
        }
        __syncthreads();
        // rows i != k: M[i][j] = (j==k ? 0 : M[i][j]) - fc[i]*M[k][j]
        for (int idx = t; idx < NN * NN; idx += 128) {
            int i = idx >> 6, j = idx & 63;
            if (i == k) continue;
            float2 f = fc[hl][i];
            float2 rk = M[k * 65 + j];
            float2 v = (j == k) ? make_float2(0.0f, 0.0f) : M[i * 65 + j];
            v.x -= f.x * rk.x - f.y * rk.y;
            v.y -= f.x * rk.y + f.y * rk.x;
            M[i * 65 + j] = v;
        }
        __syncthreads();
    }

    // dA = 2*inv - I
    float2* dAo = ((float2*)dAg) + (size_t)h * NN * NN;
    for (int idx = t; idx < NN * NN; idx += 128) {
        int i = idx >> 6, j = idx & 63;
        float2 v = M[i * 65 + j];
        dAo[idx] = make_float2(2.0f * v.x - ((i == j) ? 1.0f : 0.0f), 2.0f * v.y);
    }
    // dB = dt * inv * Bc
    if (t < 64) {
        float sr = 0.0f, si = 0.0f;
        for (int j = 0; j < NN; j++) {
            float2 m = M[t * 65 + j];
            float2 b = bvec[hl][j];
            sr += m.x * b.x - m.y * b.y;
            si += m.x * b.y + m.y * b.x;
        }
        ((float2*)dBg)[h * NN + t] = make_float2(dt * sr, dt * si);
    }
}

// ---------------------------------------------------------------------------
// Kernel 2: sequential scan, 2 heads/block (128 thr/head), 128 blocks.
// Thread owns rows {n0,n0+1} x cols [16q,16q+16). A stored once as (ar,ai);
// complex MAC via P/Q accumulators:
//   P += (ar,ai)*xr, Q += (ar,ai)*xi ; re = P.lo - Q.hi, im = P.hi + Q.lo
// x stored packed (xr,xi) per u64, chunked layout (4 chunks of 16, stride 18)
// for conflict-free broadcast LDS.128 and aligned owner STS.128.
// ---------------------------------------------------------------------------
__global__ void __launch_bounds__(256, 1) scan_kernel(const float* __restrict__ C,
                                                      float* __restrict__ out) {
    __shared__ __align__(16) u64 xbuf[2][2][72];  // [buf][head][4*18]
    __shared__ float kpart[2][2][4];
    __shared__ float psum[2][64];

    const int tid = threadIdx.x;
    const int hl = tid >> 7;
    const int t = tid & 127;
    const int warp = t >> 5;
    const int lane = t & 31;
    const int q = lane & 3;       // col slice [16q, 16q+16)
    const int rg = lane >> 2;     // 0..7
    const int n0 = warp * 16 + rg * 2;
    const int h = blockIdx.x * 2 + hl;

    // loop-invariant A block in registers (2 rows x 16 cols, packed (ar,ai))
    const float2* Ah = ((const float2*)dAg) + (size_t)h * NN * NN;
    u64 a[2][16];
#pragma unroll
    for (int r = 0; r < 2; r++) {
        const float2* row = Ah + (n0 + r) * NN + 16 * q;
#pragma unroll
        for (int j = 0; j < 16; j++) {
            float2 v = row[j];
            a[r][j] = pack2(v.x, v.y);
        }
    }
    const float2 c0 = ((const float2*)C)[h * NN + n0];
    const float2 c1 = ((const float2*)C)[h * NN + n0 + 1];

    // init x = dB, k[0] = Re(C . dB)
    if (t < 64) {
        float2 b = ((const float2*)dBg)[h * NN + t];
        xbuf[0][hl][(t >> 4) * 18 + (t & 15)] = pack2(b.x, b.y);
        float2 cc = ((const float2*)C)[h * NN + t];
        psum[hl][t] = cc.x * b.x - cc.y * b.y;
    }
    __syncthreads();
    float* outh = out + (size_t)h * LL;
    if (t == 0) {
        float s = 0.0f;
#pragma unroll 8
        for (int i = 0; i < NN; i++) s += psum[hl][i];
        outh[0] = s;
    }

    const u64* xrd[2] = { xbuf[0][hl] + q * 18, xbuf[1][hl] + q * 18 };
    u64* xwr[2] = { xbuf[0][hl] + warp * 18 + rg * 2,
                    xbuf[1][hl] + warp * 18 + rg * 2 };

#pragma unroll 1
    for (int l = 1; l < LL; l++) {
        const int pb = (l - 1) & 1;
        const int nb = l & 1;
        const u64* X = xrd[pb];

        u64 xv[16];
#pragma unroll
        for (int i = 0; i < 8; i++) {
            ulonglong2 v = *reinterpret_cast<const ulonglong2*>(X + 2 * i);
            xv[2 * i] = v.x;
            xv[2 * i + 1] = v.y;
        }

        u64 Pa0 = 0, Pb0 = 0, Qa0 = 0, Qb0 = 0;
        u64 Pa1 = 0, Pb1 = 0, Qa1 = 0, Qb1 = 0;
#pragma unroll
        for (int j = 0; j < 16; j += 2) {
            float xr, xi;
            unpack2(xv[j], xr, xi);
            u64 rr = pack2(xr, xr), ii = pack2(xi, xi);
            Pa0 = fma2(rr, a[0][j], Pa0);
            Qa0 = fma2(ii, a[0][j], Qa0);
            Pa1 = fma2(rr, a[1][j], Pa1);
            Qa1 = fma2(ii, a[1][j], Qa1);
            unpack2(xv[j + 1], xr, xi);
            rr = pack2(xr, xr); ii = pack2(xi, xi);
            Pb0 = fma2(rr, a[0][j + 1], Pb0);
            Qb0 = fma2(ii, a[0][j + 1], Qb0);
            Pb1 = fma2(rr, a[1][j + 1], Pb1);
            Qb1 = fma2(ii, a[1][j + 1], Qb1);
        }
        u64 P0 = add2(Pa0, Pb0), Q0 = add2(Qa0, Qb0);
        u64 P1 = add2(Pa1, Pb1), Q1 = add2(Qa1, Qb1);
        float p0l, p0h, q0l, q0h, p1l, p1h, q1l, q1h;
        unpack2(P0, p0l, p0h); unpack2(Q0, q0l, q0h);
        unpack2(P1, p1l, p1h); unpack2(Q1, q1l, q1h);
        float r0 = p0l - q0h, i0 = p0h + q0l;
        float r1 = p1l - q1h, i1 = p1h + q1l;

        // reduce over 4 col-slices (lanes differing in bits 0,1)
#pragma unroll
        for (int s = 1; s < 4; s <<= 1) {
            r0 += __shfl_xor_sync(0xffffffffu, r0, s);
            i0 += __shfl_xor_sync(0xffffffffu, i0, s);
            r1 += __shfl_xor_sync(0xffffffffu, r1, s);
            i1 += __shfl_xor_sync(0xffffffffu, i1, s);
        }
        if (q == 0) {
            ulonglong2 w;
            w.x = pack2(r0, i0);
            w.y = pack2(r1, i1);
            *reinterpret_cast<ulonglong2*>(xwr[nb]) = w;
        }
        // k partial: every lane has the reduced values; sum the 8 row-groups
        float kp = c0.x * r0 - c0.y * i0 + c1.x * r1 - c1.y * i1;
        kp += __shfl_xor_sync(0xffffffffu, kp, 4);
        kp += __shfl_xor_sync(0xffffffffu, kp, 8);
        kp += __shfl_xor_sync(0xffffffffu, kp, 16);
        if (lane == 0) kpart[nb][hl][warp] = kp;
        __syncthreads();
        if (t == 0) {
            outh[l] = kpart[nb][hl][0] + kpart[nb][hl][1]
                    + kpart[nb][hl][2] + kpart[nb][hl][3];
        }
    }
}

// ---------------------------------------------------------------------------

static const int SETUP_SMEM = 2 * 64 * 65 * (int)sizeof(float2);  // 66560

extern "C" void kernel_launch(void* const* d_in, const int* in_sizes, int n_in,
                              void* d_out, int out_size) {
    (void)in_sizes; (void)n_in; (void)out_size;
    const float* A     = (const float*)d_in[0];
    const float* B     = (const float*)d_in[1];
    const float* C     = (const float*)d_in[2];
    const float* logdt = (const float*)d_in[3];

    cudaFuncSetAttribute(setup_kernel, cudaFuncAttributeMaxDynamicSharedMemorySize,
                         SETUP_SMEM);
    setup_kernel<<<HH / 2, 256, SETUP_SMEM>>>(A, B, logdt);
    scan_kernel<<<HH / 2, 256>>>(C, (float*)d_out);
}

// round 3
// speedup vs baseline: 2.5822x; 2.0543x over previous
#include <cuda_runtime.h>
#include <cstdint>

#define HH 256
#define NN 64
#define LL 2048
#define PAD 66      // float2 row stride (conflict-breaking padding)

typedef unsigned long long u64;

__device__ __forceinline__ u64 fma2(u64 a, u64 b, u64 c) {
    u64 d;
    asm("fma.rn.f32x2 %0, %1, %2, %3;" : "=l"(d) : "l"(a), "l"(b), "l"(c));
    return d;
}
__device__ __forceinline__ u64 pack2(float lo, float hi) {
    u64 r;
    asm("mov.b64 %0, {%1, %2};" : "=l"(r) : "f"(lo), "f"(hi));
    return r;
}
__device__ __forceinline__ void unpack2(u64 v, float& lo, float& hi) {
    asm("mov.b64 {%0, %1}, %2;" : "=f"(lo), "=f"(hi) : "l"(v));
}

// 64x64x64 complex GEMM in smem: dst = src * src. 256 threads,
// thread tile 4x4; fma2 P/Q accumulators: per output
//   P += (ar,ai)*(br,br), Q += (ar,ai)*(bi,bi); re=P.lo-Q.hi, im=P.hi+Q.lo
__device__ __forceinline__ void square64(const float2* __restrict__ src,
                                         float2* __restrict__ dst, int t) {
    const int i0 = (t >> 4) * 4;
    const int j0 = (t & 15) * 4;
    u64 P[4][4], Q[4][4];
#pragma unroll
    for (int r = 0; r < 4; r++)
#pragma unroll
        for (int c = 0; c < 4; c++) { P[r][c] = 0; Q[r][c] = 0; }

    const u64* a0p = reinterpret_cast<const u64*>(src + (i0 + 0) * PAD);
    const u64* a1p = reinterpret_cast<const u64*>(src + (i0 + 1) * PAD);
    const u64* a2p = reinterpret_cast<const u64*>(src + (i0 + 2) * PAD);
    const u64* a3p = reinterpret_cast<const u64*>(src + (i0 + 3) * PAD);
#pragma unroll 4
    for (int k = 0; k < 64; k++) {
        u64 a[4];
        a[0] = a0p[k]; a[1] = a1p[k]; a[2] = a2p[k]; a[3] = a3p[k];
        float4 b01 = *reinterpret_cast<const float4*>(src + k * PAD + j0);
        float4 b23 = *reinterpret_cast<const float4*>(src + k * PAD + j0 + 2);
        u64 br[4], bi[4];
        br[0] = pack2(b01.x, b01.x); bi[0] = pack2(b01.y, b01.y);
        br[1] = pack2(b01.z, b01.z); bi[1] = pack2(b01.w, b01.w);
        br[2] = pack2(b23.x, b23.x); bi[2] = pack2(b23.y, b23.y);
        br[3] = pack2(b23.z, b23.z); bi[3] = pack2(b23.w, b23.w);
#pragma unroll
        for (int r = 0; r < 4; r++)
#pragma unroll
            for (int c = 0; c < 4; c++) {
                P[r][c] = fma2(a[r], br[c], P[r][c]);
                Q[r][c] = fma2(a[r], bi[c], Q[r][c]);
            }
    }
#pragma unroll
    for (int r = 0; r < 4; r++)
#pragma unroll
        for (int c = 0; c < 4; c++) {
            float pl, ph, ql, qh;
            unpack2(P[r][c], pl, ph);
            unpack2(Q[r][c], ql, qh);
            dst[(i0 + r) * PAD + j0 + c] = make_float2(pl - qh, ph + ql);
        }
}

// U doubling stage: U[s+j][n] = sum_k U[j][k] * E[k][n], j in [0,s)
__device__ __forceinline__ void ustage(float2* __restrict__ U,
                                       const float2* __restrict__ E,
                                       int s, int t) {
    for (int o = t; o < s * 64; o += 256) {
        int j = o >> 6, n = o & 63;
        const float2* uj = U + j * PAD;
        float sr = 0.f, si = 0.f;
#pragma unroll 8
        for (int k = 0; k < 64; k++) {
            float2 u = uj[k];
            float2 e = E[k * PAD + n];
            sr += u.x * e.x - u.y * e.y;
            si += u.x * e.y + u.y * e.x;
        }
        U[(s + j) * PAD + n] = make_float2(sr, si);
    }
}

// ---------------------------------------------------------------------------
// One block per head. Phases:
//  1) A_back = I - dt/2 A in smem; Gauss-Jordan in-place inverse (no pivot)
//  2) dB = dt*inv*B;  dA = 2*inv - I
//  3) squarings E2..E32 (fma2 GEMM), progressive U doubling (32 u-vectors)
//  4) v-chain: 64 steps v<-E32*v fused with output row k[32i+j]=Re(u_j . v_i)
// ---------------------------------------------------------------------------
__global__ void __launch_bounds__(256, 2) ssm_kernel(const float* __restrict__ A,
                                                     const float* __restrict__ B,
                                                     const float* __restrict__ C,
                                                     const float* __restrict__ logdt,
                                                     float* __restrict__ out) {
    extern __shared__ float2 sh[];
    float2* bufA = sh;                 // 64*PAD
    float2* bufB = bufA + 64 * PAD;    // 64*PAD
    float2* U    = bufB + 64 * PAD;    // 32*PAD
    float2* xc   = U + 32 * PAD;       // 64
    float2* xn   = xc + 64;            // 64
    float2* g    = xn + 64;            // 64
    float2* rk   = g + 64;             // 64
    float2* bv   = rk + 64;            // 64
    __shared__ float2 pivs;
    __shared__ float dts;

    const int t = threadIdx.x;
    const int h = blockIdx.x;

    if (t == 0) dts = expf(logdt[h]);
    if (t < 64) bv[t] = ((const float2*)B)[h * NN + t];
    __syncthreads();
    const float dt = dts;
    const float hd = 0.5f * dt;

    const float2* Ah = ((const float2*)A) + (size_t)h * NN * NN;
    for (int idx = t; idx < NN * NN; idx += 256) {
        int i = idx >> 6, j = idx & 63;
        float2 a = Ah[idx];
        float d = (i == j) ? 1.0f : 0.0f;
        bufA[i * PAD + j] = make_float2(d - hd * a.x, -hd * a.y);
    }
    __syncthreads();

    // ---- Gauss-Jordan in-place inversion ----
    for (int k = 0; k < NN; k++) {
        if (t < 64) {
            float2 p = bufA[k * PAD + k];
            float inv = 1.0f / (p.x * p.x + p.y * p.y);
            float2 pinv = make_float2(p.x * inv, -p.y * inv);
            if (t == 0) pivs = pinv;
            float2 m = bufA[t * PAD + k];
            g[t] = make_float2(m.x * pinv.x - m.y * pinv.y,
                               m.x * pinv.y + m.y * pinv.x);
        } else if (t < 128) {
            rk[t - 64] = bufA[k * PAD + (t - 64)];
        }
        __syncthreads();
        {
            const int i = t >> 2;
            const int j0 = (t & 3) * 16;
            const float2 pinv = pivs;
            float2* row = bufA + i * PAD;
            if (i == k) {
#pragma unroll
                for (int jj = 0; jj < 16; jj++) {
                    int j = j0 + jj;
                    float2 r = rk[j];
                    float2 nv = (j == k)
                        ? pinv
                        : make_float2(r.x * pinv.x - r.y * pinv.y,
                                      r.x * pinv.y + r.y * pinv.x);
                    row[j] = nv;
                }
            } else {
                float2 gi = g[i];
#pragma unroll
                for (int jj = 0; jj < 16; jj++) {
                    int j = j0 + jj;
                    float2 r = rk[j];
                    float2 v = row[j];
                    float2 nv;
                    if (j == k) nv = make_float2(-gi.x, -gi.y);
                    else nv = make_float2(v.x - (gi.x * r.x - gi.y * r.y),
                                          v.y - (gi.x * r.y + gi.y * r.x));
                    row[j] = nv;
                }
            }
        }
        __syncthreads();
    }

    // ---- dB = dt * inv * B -> xc ----
    {
        const int rr = t >> 2, sg = t & 3;
        const float2* mr = bufA + rr * PAD + sg * 16;
        float sr = 0.f, si = 0.f;
#pragma unroll
        for (int kk = 0; kk < 16; kk++) {
            float2 m = mr[kk];
            float2 b = bv[sg * 16 + kk];
            sr += m.x * b.x - m.y * b.y;
            si += m.x * b.y + m.y * b.x;
        }
#pragma unroll
        for (int s = 1; s < 4; s <<= 1) {
            sr += __shfl_xor_sync(0xffffffffu, sr, s);
            si += __shfl_xor_sync(0xffffffffu, si, s);
        }
        if (sg == 0) xc[rr] = make_float2(dt * sr, dt * si);
    }
    __syncthreads();

    // ---- dA = 2*inv - I (in place), U[0] = C ----
    for (int idx = t; idx < NN * NN; idx += 256) {
        int i = idx >> 6, j = idx & 63;
        float2 v = bufA[i * PAD + j];
        bufA[i * PAD + j] = make_float2(2.0f * v.x - ((i == j) ? 1.0f : 0.0f),
                                        2.0f * v.y);
    }
    if (t < 64) U[t] = ((const float2*)C)[h * NN + t];
    __syncthreads();

    // ---- powers + U doubling ----
    ustage(U, bufA, 1, t);  __syncthreads();   // uses E1 = dA
    square64(bufA, bufB, t); __syncthreads();  // E2
    ustage(U, bufB, 2, t);  __syncthreads();
    square64(bufB, bufA, t); __syncthreads();  // E4
    ustage(U, bufA, 4, t);  __syncthreads();
    square64(bufA, bufB, t); __syncthreads();  // E8
    ustage(U, bufB, 8, t);  __syncthreads();
    square64(bufB, bufA, t); __syncthreads();  // E16
    ustage(U, bufA, 16, t); __syncthreads();
    square64(bufA, bufB, t); __syncthreads();  // E32 in bufB

    // ---- v-chain fused with output GEMM ----
    float* outh = out + (size_t)h * LL;
    float2* xcur = xc;
    float2* xnxt = xn;
    const int j_out = t >> 3, seg8 = t & 7;
    const int rr = t >> 2, sg4 = t & 3;

    for (int i = 0; i < 64; i++) {
        // k[32*i + j] = Re(sum_n U[j][n] * v[n])
        {
            const float2* uj = U + j_out * PAD + seg8 * 8;
            const float2* xv = xcur + seg8 * 8;
            float kp = 0.f;
#pragma unroll
            for (int n = 0; n < 8; n++) {
                float2 u = uj[n];
                float2 x = xv[n];
                kp += u.x * x.x - u.y * x.y;
            }
            kp += __shfl_xor_sync(0xffffffffu, kp, 1);
            kp += __shfl_xor_sync(0xffffffffu, kp, 2);
            kp += __shfl_xor_sync(0xffffffffu, kp, 4);
            if (seg8 == 0) outh[i * 32 + j_out] = kp;
        }
        // v <- E32 * v
        if (i < 63) {
            const float2* er = bufB + rr * PAD + sg4 * 16;
            const float2* xv = xcur + sg4 * 16;
            float sr = 0.f, si = 0.f;
#pragma unroll
            for (int kk = 0; kk < 16; kk++) {
                float2 e = er[kk];
                float2 x = xv[kk];
                sr += e.x * x.x - e.y * x.y;
                si += e.x * x.y + e.y * x.x;
            }
            sr += __shfl_xor_sync(0xffffffffu, sr, 1);
            si += __shfl_xor_sync(0xffffffffu, si, 1);
            sr += __shfl_xor_sync(0xffffffffu, sr, 2);
            si += __shfl_xor_sync(0xffffffffu, si, 2);
            if (sg4 == 0) xnxt[rr] = make_float2(sr, si);
        }
        __syncthreads();
        float2* tmp = xcur; xcur = xnxt; xnxt = tmp;
    }
}

// ---------------------------------------------------------------------------

static const int SSM_SMEM = (2 * 64 * PAD + 32 * PAD + 5 * 64) * (int)sizeof(float2);

extern "C" void kernel_launch(void* const* d_in, const int* in_sizes, int n_in,
                              void* d_out, int out_size) {
    (void)in_sizes; (void)n_in; (void)out_size;
    const float* A     = (const float*)d_in[0];
    const float* B     = (const float*)d_in[1];
    const float* C     = (const float*)d_in[2];
    const float* logdt = (const float*)d_in[3];

    cudaFuncSetAttribute(ssm_kernel, cudaFuncAttributeMaxDynamicSharedMemorySize,
                         SSM_SMEM);
    ssm_kernel<<<HH, 256, SSM_SMEM>>>(A, B, C, logdt, (float*)d_out);
}

// round 6
// speedup vs baseline: 3.8773x; 1.5015x over previous
#include <cuda_runtime.h>
#include <cstdint>

#define HH 256
#define NN 64
#define LL 2048
#define PAD 66      // float2 row stride for matrices (conflict-breaking, even)

typedef unsigned long long u64;

__device__ __forceinline__ u64 fma2(u64 a, u64 b, u64 c) {
    u64 d;
    asm("fma.rn.f32x2 %0, %1, %2, %3;" : "=l"(d) : "l"(a), "l"(b), "l"(c));
    return d;
}
__device__ __forceinline__ u64 add2(u64 a, u64 b) {
    u64 d;
    asm("add.rn.f32x2 %0, %1, %2;" : "=l"(d) : "l"(a), "l"(b));
    return d;
}
__device__ __forceinline__ u64 pack2(float lo, float hi) {
    u64 r;
    asm("mov.b64 %0, {%1, %2};" : "=l"(r) : "f"(lo), "f"(hi));
    return r;
}
__device__ __forceinline__ void unpack2(u64 v, float& lo, float& hi) {
    asm("mov.b64 {%0, %1}, %2;" : "=f"(lo), "=f"(hi) : "l"(v));
}

// 64x64x64 complex GEMM in smem: dst = src*src. Thread tile 4x4.
// P += (ar,ai)*(br,br), Q += (ar,ai)*(bi,bi); re=P.lo-Q.hi, im=P.hi+Q.lo
__device__ __forceinline__ void square64(const float2* __restrict__ src,
                                         float2* __restrict__ dst, int t) {
    const int i0 = (t >> 4) * 4;
    const int j0 = (t & 15) * 4;
    u64 P[4][4], Q[4][4];
#pragma unroll
    for (int r = 0; r < 4; r++)
#pragma unroll
        for (int c = 0; c < 4; c++) { P[r][c] = 0; Q[r][c] = 0; }

#pragma unroll 2
    for (int k = 0; k < 64; k += 2) {
        u64 a[4][2];
#pragma unroll
        for (int r = 0; r < 4; r++) {
            ulonglong2 av = *reinterpret_cast<const ulonglong2*>(
                reinterpret_cast<const u64*>(src + (i0 + r) * PAD) + k);
            a[r][0] = av.x; a[r][1] = av.y;
        }
#pragma unroll
        for (int kk = 0; kk < 2; kk++) {
            float4 b01 = *reinterpret_cast<const float4*>(src + (k + kk) * PAD + j0);
            float4 b23 = *reinterpret_cast<const float4*>(src + (k + kk) * PAD + j0 + 2);
            u64 br0 = pack2(b01.x, b01.x), bi0 = pack2(b01.y, b01.y);
            u64 br1 = pack2(b01.z, b01.z), bi1 = pack2(b01.w, b01.w);
            u64 br2 = pack2(b23.x, b23.x), bi2 = pack2(b23.y, b23.y);
            u64 br3 = pack2(b23.z, b23.z), bi3 = pack2(b23.w, b23.w);
#pragma unroll
            for (int r = 0; r < 4; r++) {
                P[r][0] = fma2(a[r][kk], br0, P[r][0]);
                Q[r][0] = fma2(a[r][kk], bi0, Q[r][0]);
                P[r][1] = fma2(a[r][kk], br1, P[r][1]);
                Q[r][1] = fma2(a[r][kk], bi1, Q[r][1]);
                P[r][2] = fma2(a[r][kk], br2, P[r][2]);
                Q[r][2] = fma2(a[r][kk], bi2, Q[r][2]);
                P[r][3] = fma2(a[r][kk], br3, P[r][3]);
                Q[r][3] = fma2(a[r][kk], bi3, Q[r][3]);
            }
        }
    }
#pragma unroll
    for (int r = 0; r < 4; r++) {
        float re[4], im[4];
#pragma unroll
        for (int c = 0; c < 4; c++) {
            float pl, ph, ql, qh;
            unpack2(P[r][c], pl, ph);
            unpack2(Q[r][c], ql, qh);
            re[c] = pl - qh; im[c] = ph + ql;
        }
        *reinterpret_cast<float4*>(dst + (i0 + r) * PAD + j0) =
            make_float4(re[0], im[0], re[1], im[1]);
        *reinterpret_cast<float4*>(dst + (i0 + r) * PAD + j0 + 2) =
            make_float4(re[2], im[2], re[3], im[3]);
    }
}

// U doubling, small stages s in {1,2,4,8}: U[s+j][n] = sum_k U[j][k]*E[k][n]
__device__ __forceinline__ void ustage_small(float2* __restrict__ U,
                                             const float2* __restrict__ E,
                                             int s, int t) {
    for (int o = t; o < s * 64; o += 256) {
        int j = o >> 6, n = o & 63;
        const float2* uj = U + j * PAD;
        float sr = 0.f, si = 0.f;
#pragma unroll 8
        for (int k = 0; k < 64; k++) {
            float2 u = uj[k];
            float2 e = E[k * PAD + n];
            sr += u.x * e.x - u.y * e.y;
            si += u.x * e.y + u.y * e.x;
        }
        U[(s + j) * PAD + n] = make_float2(sr, si);
    }
}

// U doubling stage s=16, fma2 GEMM: thread = (row j = t>>4, cols n0..n0+4)
__device__ __forceinline__ void ustage16(float2* __restrict__ U,
                                         const float2* __restrict__ E, int t) {
    const int j = t >> 4;
    const int n0 = (t & 15) * 4;
    u64 P[4] = {0, 0, 0, 0}, Q[4] = {0, 0, 0, 0};
    const float2* uj = U + j * PAD;
#pragma unroll 4
    for (int k = 0; k < 64; k++) {
        float2 u = uj[k];
        u64 ur = pack2(u.x, u.x), ui = pack2(u.y, u.y);
        float4 e01 = *reinterpret_cast<const float4*>(E + k * PAD + n0);
        float4 e23 = *reinterpret_cast<const float4*>(E + k * PAD + n0 + 2);
        u64 e0 = pack2(e01.x, e01.y), e1 = pack2(e01.z, e01.w);
        u64 e2 = pack2(e23.x, e23.y), e3 = pack2(e23.z, e23.w);
        P[0] = fma2(e0, ur, P[0]); Q[0] = fma2(e0, ui, Q[0]);
        P[1] = fma2(e1, ur, P[1]); Q[1] = fma2(e1, ui, Q[1]);
        P[2] = fma2(e2, ur, P[2]); Q[2] = fma2(e2, ui, Q[2]);
        P[3] = fma2(e3, ur, P[3]); Q[3] = fma2(e3, ui, Q[3]);
    }
    float re[4], im[4];
#pragma unroll
    for (int c = 0; c < 4; c++) {
        float pl, ph, ql, qh;
        unpack2(P[c], pl, ph);
        unpack2(Q[c], ql, qh);
        re[c] = pl - qh; im[c] = ph + ql;
    }
    *reinterpret_cast<float4*>(U + (16 + j) * PAD + n0) =
        make_float4(re[0], im[0], re[1], im[1]);
    *reinterpret_cast<float4*>(U + (16 + j) * PAD + n0 + 2) =
        make_float4(re[2], im[2], re[3], im[3]);
}

// ---------------------------------------------------------------------------
// One block per head.
//  1) register-resident Gauss-Jordan inverse of A_back (thread owns 16 elems)
//  2) dB = dt*inv*B (register dot + shfl); dA = 2*inv - I -> smem
//  3) squarings E2..E32 fused with progressive U doubling (32 u-vectors)
//  4) v-chain: 64 steps v<-E32*v (E32 slice register-cached) fused with
//     output k[32i+j] = Re(u_j . v_i)
// ---------------------------------------------------------------------------
__global__ void __launch_bounds__(256, 2) ssm_kernel(const float* __restrict__ A,
                                                     const float* __restrict__ B,
                                                     const float* __restrict__ C,
                                                     const float* __restrict__ logdt,
                                                     float* __restrict__ out) {
    extern __shared__ float2 sh[];
    float2* bufA  = sh;                  // 64*PAD
    float2* bufB  = bufA + 64 * PAD;     // 64*PAD
    float2* U     = bufB + 64 * PAD;     // 32*PAD
    float2* xbuf0 = U + 32 * PAD;        // 64
    float2* xbuf1 = xbuf0 + 64;          // 64
    float2* gbuf  = xbuf1 + 64;          // 2*64 (col-k factors, dbl-buffered)
    float2* rkbuf = gbuf + 128;          // 2*64 (row-k raw, dbl-buffered)
    float2* bv    = rkbuf + 128;         // 64

    const int t = threadIdx.x;
    const int h = blockIdx.x;
    const int i = t >> 2;    // owned row
    const int sg = t & 3;    // owned col segment [16*sg, 16*sg+16)

    const float dt = expf(__ldg(logdt + h));
    const float hd = 0.5f * dt;

    // stage A (coalesced) + B + C
    const float2* Ah = ((const float2*)A) + (size_t)h * NN * NN;
    for (int idx = t; idx < NN * NN; idx += 256) bufA[idx] = Ah[idx];
    if (t < 64) {
        bv[t] = ((const float2*)B)[h * NN + t];
        U[t]  = ((const float2*)C)[h * NN + t];
    }
    __syncthreads();

    // registers <- A_back = I - dt/2 * Ac
    float2 R[16];
#pragma unroll
    for (int jj = 0; jj < 16; jj++) {
        int j = sg * 16 + jj;
        float2 a = bufA[i * 64 + j];
        R[jj] = make_float2(((i == j) ? 1.0f : 0.0f) - hd * a.x, -hd * a.y);
    }
    __syncthreads();

    // ---- register-resident Gauss-Jordan inverse (no pivoting) ----
#pragma unroll 1
    for (int k = 0; k < NN; k++) {
        const int pb = k & 1;
        const int ks = k >> 4, kj = k & 15;
        if (sg == ks) gbuf[pb * 64 + i] = R[kj];
        if (i == k) {
#pragma unroll
            for (int jj = 0; jj < 16; jj++) rkbuf[pb * 64 + sg * 16 + jj] = R[jj];
        }
        __syncthreads();
        float2 p = gbuf[pb * 64 + k];
        float inv = 1.0f / (p.x * p.x + p.y * p.y);
        float2 pinv = make_float2(p.x * inv, -p.y * inv);
        if (i == k) {
#pragma unroll
            for (int jj = 0; jj < 16; jj++) {
                int j = sg * 16 + jj;
                float2 r = R[jj];
                R[jj] = (j == k) ? pinv
                                 : make_float2(r.x * pinv.x - r.y * pinv.y,
                                               r.x * pinv.y + r.y * pinv.x);
            }
        } else {
            float2 gi = gbuf[pb * 64 + i];
            float2 fc = make_float2(gi.x * pinv.x - gi.y * pinv.y,
                                    gi.x * pinv.y + gi.y * pinv.x);
#pragma unroll
            for (int jj = 0; jj < 16; jj++) {
                int j = sg * 16 + jj;
                float2 r = rkbuf[pb * 64 + j];
                float2 v = R[jj];
                if (j == k) {
                    R[jj] = make_float2(-fc.x, -fc.y);
                } else {
                    v.x -= fc.x * r.x - fc.y * r.y;
                    v.y -= fc.x * r.y + fc.y * r.x;
                    R[jj] = v;
                }
            }
        }
    }

    // ---- dB = dt * inv * B (register dot, reduce over 4 col segments) ----
    {
        float sr = 0.f, si = 0.f;
#pragma unroll
        for (int jj = 0; jj < 16; jj++) {
            float2 m = R[jj];
            float2 b = bv[sg * 16 + jj];
            sr += m.x * b.x - m.y * b.y;
            si += m.x * b.y + m.y * b.x;
        }
        sr += __shfl_xor_sync(0xffffffffu, sr, 1);
        si += __shfl_xor_sync(0xffffffffu, si, 1);
        sr += __shfl_xor_sync(0xffffffffu, sr, 2);
        si += __shfl_xor_sync(0xffffffffu, si, 2);
        if (sg == 0) xbuf0[i] = make_float2(dt * sr, dt * si);
    }
    // ---- dA = 2*inv - I -> bufA (padded) ----
#pragma unroll
    for (int jj = 0; jj < 16; jj++) {
        int j = sg * 16 + jj;
        bufA[i * PAD + j] = make_float2(2.0f * R[jj].x - ((i == j) ? 1.0f : 0.0f),
                                        2.0f * R[jj].y);
    }
    __syncthreads();

    // ---- fused powers + U doubling ----
    ustage_small(U, bufA, 1, t); square64(bufA, bufB, t); __syncthreads(); // E2
    ustage_small(U, bufB, 2, t); square64(bufB, bufA, t); __syncthreads(); // E4
    ustage_small(U, bufA, 4, t); square64(bufA, bufB, t); __syncthreads(); // E8
    ustage_small(U, bufB, 8, t); square64(bufB, bufA, t); __syncthreads(); // E16
    ustage16(U, bufA, t);        square64(bufA, bufB, t); __syncthreads(); // E32

    // ---- v-chain with register-cached E32 slice ----
    u64 e[16];
    {
        const float2* er = bufB + i * PAD + sg * 16;
#pragma unroll
        for (int kk = 0; kk < 16; kk++) {
            float2 v = er[kk];
            e[kk] = pack2(v.x, v.y);
        }
    }
    const int j_out = t >> 3, seg8 = t & 7;
    float* outh = out + (size_t)h * LL;
    float2* xcur = xbuf0;
    float2* xnxt = xbuf1;

#pragma unroll 1
    for (int it = 0; it < 64; it++) {
        // k[32*it + j_out] = Re(U[j_out] . v)
        {
            const float4* uu = reinterpret_cast<const float4*>(U + j_out * PAD + seg8 * 8);
            const float4* xx = reinterpret_cast<const float4*>(xcur + seg8 * 8);
            float kp = 0.f;
#pragma unroll
            for (int m = 0; m < 4; m++) {
                float4 u2 = uu[m];
                float4 x2 = xx[m];
                kp += u2.x * x2.x - u2.y * x2.y + u2.z * x2.z - u2.w * x2.w;
            }
            kp += __shfl_xor_sync(0xffffffffu, kp, 1);
            kp += __shfl_xor_sync(0xffffffffu, kp, 2);
            kp += __shfl_xor_sync(0xffffffffu, kp, 4);
            if (seg8 == 0) outh[it * 32 + j_out] = kp;
        }
        // v <- E32 * v
        if (it < 63) {
            const float4* xv = reinterpret_cast<const float4*>(xcur + sg * 16);
            u64 P0 = 0, Q0 = 0, P1 = 0, Q1 = 0;
#pragma unroll
            for (int m = 0; m < 8; m++) {
                float4 x2 = xv[m];
                u64 xr0 = pack2(x2.x, x2.x), xi0 = pack2(x2.y, x2.y);
                u64 xr1 = pack2(x2.z, x2.z), xi1 = pack2(x2.w, x2.w);
                P0 = fma2(e[2 * m],     xr0, P0);
                Q0 = fma2(e[2 * m],     xi0, Q0);
                P1 = fma2(e[2 * m + 1], xr1, P1);
                Q1 = fma2(e[2 * m + 1], xi1, Q1);
            }
            u64 P = add2(P0, P1), Q = add2(Q0, Q1);
            float pl, ph, ql, qh;
            unpack2(P, pl, ph);
            unpack2(Q, ql, qh);
            float re = pl - qh, im = ph + ql;
            re += __shfl_xor_sync(0xffffffffu, re, 1);
            im += __shfl_xor_sync(0xffffffffu, im, 1);
            re += __shfl_xor_sync(0xffffffffu, re, 2);
            im += __shfl_xor_sync(0xffffffffu, im, 2);
            if (sg == 0) xnxt[i] = make_float2(re, im);
        }
        __syncthreads();
        float2* tmp = xcur; xcur = xnxt; xnxt = tmp;
    }
}

// ---------------------------------------------------------------------------

static const int SSM_SMEM =
    (2 * 64 * PAD + 32 * PAD + 2 * 64 + 2 * 128 + 64) * (int)sizeof(float2);

extern "C" void kernel_launch(void* const* d_in, const int* in_sizes, int n_in,
                              void* d_out, int out_size) {
    (void)in_sizes; (void)n_in; (void)out_size;
    const float* A     = (const float*)d_in[0];
    const float* B     = (const float*)d_in[1];
    const float* C     = (const float*)d_in[2];
    const float* logdt = (const float*)d_in[3];

    cudaFuncSetAttribute(ssm_kernel, cudaFuncAttributeMaxDynamicSharedMemorySize,
                         SSM_SMEM);
    ssm_kernel<<<HH, 256, SSM_SMEM>>>(A, B, C, logdt, (float*)d_out);
}

// round 8
// speedup vs baseline: 3.8932x; 1.0041x over previous
#include <cuda_runtime.h>
#include <cstdint>

#define HH 256
#define NN 64
#define LL 2048
#define PAD 66      // float2 row stride (even, conflict-breaking)
#define TT 512

typedef unsigned long long u64;

__device__ __forceinline__ u64 fma2(u64 a, u64 b, u64 c) {
    u64 d;
    asm("fma.rn.f32x2 %0, %1, %2, %3;" : "=l"(d) : "l"(a), "l"(b), "l"(c));
    return d;
}
__device__ __forceinline__ u64 pack2(float lo, float hi) {
    u64 r;
    asm("mov.b64 %0, {%1, %2};" : "=l"(r) : "f"(lo), "f"(hi));
    return r;
}
__device__ __forceinline__ void unpack2(u64 v, float& lo, float& hi) {
    asm("mov.b64 {%0, %1}, %2;" : "=f"(lo), "=f"(hi) : "l"(v));
}

// ---------------------------------------------------------------------------
// In-place 64x64 complex square: buf <- buf * buf.
// Thread tile: rows {r0, r0+1} x cols [j0, j0+4).  512 threads cover 64x64.
// a-splat / b-pair form:
//   P[r][c] += (ar,ar)*(br,bi) ; Q[r][c] += (ai,ai)*(br,bi)
//   re = P.lo - Q.hi ; im = P.hi + Q.lo
// ---------------------------------------------------------------------------
__device__ __forceinline__ void square_ip(float2* __restrict__ buf, int t) {
    const int r0 = (t >> 4) * 2;
    const int j0 = (t & 15) * 4;
    u64 P[2][4], Q[2][4];
#pragma unroll
    for (int r = 0; r < 2; r++)
#pragma unroll
        for (int c = 0; c < 4; c++) { P[r][c] = 0; Q[r][c] = 0; }

    const u64* row0 = reinterpret_cast<const u64*>(buf + r0 * PAD);
    const u64* row1 = reinterpret_cast<const u64*>(buf + (r0 + 1) * PAD);

#pragma unroll 2
    for (int k = 0; k < 64; k += 2) {
        ulonglong2 a0 = *reinterpret_cast<const ulonglong2*>(row0 + k);
        ulonglong2 a1 = *reinterpret_cast<const ulonglong2*>(row1 + k);
#pragma unroll
        for (int kk = 0; kk < 2; kk++) {
            const u64 ap0 = kk ? a0.y : a0.x;
            const u64 ap1 = kk ? a1.y : a1.x;
            float a0r, a0i, a1r, a1i;
            unpack2(ap0, a0r, a0i);
            unpack2(ap1, a1r, a1i);
            u64 s0r = pack2(a0r, a0r), s0i = pack2(a0i, a0i);
            u64 s1r = pack2(a1r, a1r), s1i = pack2(a1i, a1i);
            const u64* bk = reinterpret_cast<const u64*>(buf + (k + kk) * PAD);
            ulonglong2 b01 = *reinterpret_cast<const ulonglong2*>(bk + j0);
            ulonglong2 b23 = *reinterpret_cast<const ulonglong2*>(bk + j0 + 2);
            P[0][0] = fma2(s0r, b01.x, P[0][0]); Q[0][0] = fma2(s0i, b01.x, Q[0][0]);
            P[0][1] = fma2(s0r, b01.y, P[0][1]); Q[0][1] = fma2(s0i, b01.y, Q[0][1]);
            P[0][2] = fma2(s0r, b23.x, P[0][2]); Q[0][2] = fma2(s0i, b23.x, Q[0][2]);
            P[0][3] = fma2(s0r, b23.y, P[0][3]); Q[0][3] = fma2(s0i, b23.y, Q[0][3]);
            P[1][0] = fma2(s1r, b01.x, P[1][0]); Q[1][0] = fma2(s1i, b01.x, Q[1][0]);
            P[1][1] = fma2(s1r, b01.y, P[1][1]); Q[1][1] = fma2(s1i, b01.y, Q[1][1]);
            P[1][2] = fma2(s1r, b23.x, P[1][2]); Q[1][2] = fma2(s1i, b23.x, Q[1][2]);
            P[1][3] = fma2(s1r, b23.y, P[1][3]); Q[1][3] = fma2(s1i, b23.y, Q[1][3]);
        }
    }
    __syncthreads();   // all reads of buf complete
#pragma unroll
    for (int r = 0; r < 2; r++) {
        float re[4], im[4];
#pragma unroll
        for (int c = 0; c < 4; c++) {
            float pl, ph, ql, qh;
            unpack2(P[r][c], pl, ph);
            unpack2(Q[r][c], ql, qh);
            re[c] = pl - qh; im[c] = ph + ql;
        }
        *reinterpret_cast<float4*>(buf + (r0 + r) * PAD + j0) =
            make_float4(re[0], im[0], re[1], im[1]);
        *reinterpret_cast<float4*>(buf + (r0 + r) * PAD + j0 + 2) =
            make_float4(re[2], im[2], re[3], im[3]);
    }
    __syncthreads();
}

// U doubling, s in {1,2,4,8}: U[s+j][n] = sum_k U[j][k] * E[k][n]
__device__ __forceinline__ void ustage_small(float2* __restrict__ U,
                                             const float2* __restrict__ E,
                                             int s, int t) {
    for (int o = t; o < s * 64; o += TT) {
        int j = o >> 6, n = o & 63;
        const float2* uj = U + j * PAD;
        float sr = 0.f, si = 0.f;
#pragma unroll 8
        for (int k = 0; k < 64; k++) {
            float2 u = uj[k];
            float2 e = E[k * PAD + n];
            sr += u.x * e.x - u.y * e.y;
            si += u.x * e.y + u.y * e.x;
        }
        U[(s + j) * PAD + n] = make_float2(sr, si);
    }
}

// U doubling s=16: thread = (row j = t>>5, col pair n0 = (t&31)*2)
__device__ __forceinline__ void ustage16(float2* __restrict__ U,
                                         const float2* __restrict__ E, int t) {
    const int j = t >> 5;
    const int n0 = (t & 31) * 2;
    u64 P0 = 0, Q0 = 0, P1 = 0, Q1 = 0;
    const float2* uj = U + j * PAD;
#pragma unroll 4
    for (int k = 0; k < 64; k++) {
        float2 u = uj[k];
        u64 ur = pack2(u.x, u.x), ui = pack2(u.y, u.y);
        ulonglong2 e = *reinterpret_cast<const ulonglong2*>(
            reinterpret_cast<const u64*>(E + k * PAD) + n0);
        P0 = fma2(ur, e.x, P0); Q0 = fma2(ui, e.x, Q0);
        P1 = fma2(ur, e.y, P1); Q1 = fma2(ui, e.y, Q1);
    }
    float p0l, p0h, q0l, q0h, p1l, p1h, q1l, q1h;
    unpack2(P0, p0l, p0h); unpack2(Q0, q0l, q0h);
    unpack2(P1, p1l, p1h); unpack2(Q1, q1l, q1h);
    *reinterpret_cast<float4*>(U + (16 + j) * PAD + n0) =
        make_float4(p0l - q0h, p0h + q0l, p1l - q1h, p1h + q1l);
}

// ---------------------------------------------------------------------------
// One block (512 threads) per head.
// ---------------------------------------------------------------------------
__global__ void __launch_bounds__(TT, 2) ssm_kernel(const float* __restrict__ A,
                                                    const float* __restrict__ B,
                                                    const float* __restrict__ C,
                                                    const float* __restrict__ logdt,
                                                    float* __restrict__ out) {
    extern __shared__ float2 sh[];
    float2* buf   = sh;                  // 64*PAD — matrix (in-place squares)
    float2* U     = buf + 64 * PAD;      // 32*PAD
    float2* xbuf0 = U + 32 * PAD;        // 64
    float2* xbuf1 = xbuf0 + 64;          // 64
    float2* gbuf  = xbuf1 + 64;          // 2*64 col-k factors (dbl-buffered)
    float2* rkbuf = gbuf + 128;          // 2*64 row-k raw (dbl-buffered)
    float2* bv    = rkbuf + 128;         // 64

    const int t = threadIdx.x;
    const int h = blockIdx.x;
    const int i  = t >> 3;   // GJ owned row
    const int sg = t & 7;    // GJ owned col segment [8*sg, 8*sg+8)

    const float dt = expf(__ldg(logdt + h));
    const float hd = 0.5f * dt;

    // stage inputs
    const float2* Ah = ((const float2*)A) + (size_t)h * NN * NN;
    for (int idx = t; idx < NN * NN; idx += TT) buf[idx] = Ah[idx];
    if (t < 64) {
        bv[t] = ((const float2*)B)[h * NN + t];
        U[t]  = ((const float2*)C)[h * NN + t];
    }
    __syncthreads();

    // registers <- A_back = I - dt/2 * Ac  (8 elems per thread)
    float2 R[8];
#pragma unroll
    for (int jj = 0; jj < 8; jj++) {
        int j = sg * 8 + jj;
        float2 a = buf[i * 64 + j];
        R[jj] = make_float2(((i == j) ? 1.0f : 0.0f) - hd * a.x, -hd * a.y);
    }
    __syncthreads();

    // ---- register-resident Gauss-Jordan inverse (no pivoting) ----
    // One barrier per iteration: gbuf/rkbuf double-buffered, so iter-k reads
    // are separated from the next write of that buffer (iter k+2) by the
    // iter-(k+1) barrier.
#pragma unroll 1
    for (int k = 0; k < NN; k++) {
        const int pb = (k & 1) * 64;
        if (sg == (k >> 3)) gbuf[pb + i] = R[k & 7];
        if (i == k) {
#pragma unroll
            for (int jj = 0; jj < 8; jj++) rkbuf[pb + sg * 8 + jj] = R[jj];
        }
        __syncthreads();
        float2 p = gbuf[pb + k];
        float inv = 1.0f / (p.x * p.x + p.y * p.y);
        float2 pinv = make_float2(p.x * inv, -p.y * inv);
        if (i == k) {
#pragma unroll
            for (int jj = 0; jj < 8; jj++) {
                int j = sg * 8 + jj;
                float2 r = R[jj];
                R[jj] = (j == k) ? pinv
                                 : make_float2(r.x * pinv.x - r.y * pinv.y,
                                               r.x * pinv.y + r.y * pinv.x);
            }
        } else {
            float2 gi = gbuf[pb + i];
            float2 fc = make_float2(gi.x * pinv.x - gi.y * pinv.y,
                                    gi.x * pinv.y + gi.y * pinv.x);
            const float4* rk4 = reinterpret_cast<const float4*>(rkbuf + pb + sg * 8);
#pragma unroll
            for (int m = 0; m < 4; m++) {
                float4 rr = rk4[m];
                float2 v0 = R[2 * m], v1 = R[2 * m + 1];
                v0.x -= fc.x * rr.x - fc.y * rr.y;
                v0.y -= fc.x * rr.y + fc.y * rr.x;
                v1.x -= fc.x * rr.z - fc.y * rr.w;
                v1.y -= fc.x * rr.w + fc.y * rr.z;
                R[2 * m] = v0; R[2 * m + 1] = v1;
            }
            // inverse-accumulation column: R[j==k] = -fc  (overwrite; the
            // vectorized update above wrote garbage there: v - fc*p)
            if (sg == (k >> 3)) R[k & 7] = make_float2(-fc.x, -fc.y);
        }
    }
    __syncthreads();

    // ---- dB = dt*inv*B (reduce over 8 col segments = lane bits 0..2) ----
    {
        float sr = 0.f, si = 0.f;
#pragma unroll
        for (int jj = 0; jj < 8; jj++) {
            float2 m = R[jj];
            float2 b = bv[sg * 8 + jj];
            sr += m.x * b.x - m.y * b.y;
            si += m.x * b.y + m.y * b.x;
        }
        sr += __shfl_xor_sync(0xffffffffu, sr, 1);
        si += __shfl_xor_sync(0xffffffffu, si, 1);
        sr += __shfl_xor_sync(0xffffffffu, sr, 2);
        si += __shfl_xor_sync(0xffffffffu, si, 2);
        sr += __shfl_xor_sync(0xffffffffu, sr, 4);
        si += __shfl_xor_sync(0xffffffffu, si, 4);
        if (sg == 0) xbuf0[i] = make_float2(dt * sr, dt * si);
    }
    // ---- dA = 2*inv - I -> buf (padded) ----
#pragma unroll
    for (int jj = 0; jj < 8; jj++) {
        int j = sg * 8 + jj;
        buf[i * PAD + j] = make_float2(2.0f * R[jj].x - ((i == j) ? 1.0f : 0.0f),
                                       2.0f * R[jj].y);
    }
    __syncthreads();

    // ---- fused powers + U doubling (E held in buf, squared in place) ----
    ustage_small(U, buf, 1, t); square_ip(buf, t);   // E2,  U[1]
    ustage_small(U, buf, 2, t); square_ip(buf, t);   // E4,  U[2..4)
    ustage_small(U, buf, 4, t); square_ip(buf, t);   // E8,  U[4..8)
    ustage_small(U, buf, 8, t); square_ip(buf, t);   // E16, U[8..16)
    ustage16(U, buf, t);        square_ip(buf, t);   // E32, U[16..32)

    // ---- v-chain: 64 iters, E32 slice register-cached ----
    u64 e[8];
    {
        const u64* er = reinterpret_cast<const u64*>(buf + i * PAD) + sg * 8;
#pragma unroll
        for (int kk = 0; kk < 8; kk++) e[kk] = er[kk];
    }
    const int j_out = t >> 4;        // 0..31
    const int s16 = t & 15;          // col segment of 4 for output dot
    float* outh = out + (size_t)h * LL;
    float2* xcur = xbuf0;
    float2* xnxt = xbuf1;

#pragma unroll 1
    for (int it = 0; it < 64; it++) {
        // k[32*it + j_out] = Re(U[j_out] . v)
        {
            const float4* uu = reinterpret_cast<const float4*>(U + j_out * PAD + s16 * 4);
            const float4* xx = reinterpret_cast<const float4*>(xcur + s16 * 4);
            float4 u0 = uu[0], u1 = uu[1];
            float4 x0 = xx[0], x1 = xx[1];
            float kp = u0.x * x0.x - u0.y * x0.y + u0.z * x0.z - u0.w * x0.w
                     + u1.x * x1.x - u1.y * x1.y + u1.z * x1.z - u1.w * x1.w;
            kp += __shfl_xor_sync(0xffffffffu, kp, 1);
            kp += __shfl_xor_sync(0xffffffffu, kp, 2);
            kp += __shfl_xor_sync(0xffffffffu, kp, 4);
            kp += __shfl_xor_sync(0xffffffffu, kp, 8);
            if (s16 == 0) outh[it * 32 + j_out] = kp;
        }
        // v <- E32 * v  (row i, 8-col slice sg; reduce over lane bits 0..2)
        if (it < 63) {
            const u64* xv = reinterpret_cast<const u64*>(xcur) + sg * 8;
            u64 P0 = 0, Q0 = 0, P1 = 0, Q1 = 0;
#pragma unroll
            for (int m = 0; m < 4; m++) {
                ulonglong2 x2 = *reinterpret_cast<const ulonglong2*>(xv + 2 * m);
                float xr, xi;
                unpack2(x2.x, xr, xi);
                P0 = fma2(pack2(xr, xr), e[2 * m], P0);
                Q0 = fma2(pack2(xi, xi), e[2 * m], Q0);
                unpack2(x2.y, xr, xi);
                P1 = fma2(pack2(xr, xr), e[2 * m + 1], P1);
                Q1 = fma2(pack2(xi, xi), e[2 * m + 1], Q1);
            }
            float p0l, p0h, q0l, q0h, p1l, p1h, q1l, q1h;
            unpack2(P0, p0l, p0h); unpack2(Q0, q0l, q0h);
            unpack2(P1, p1l, p1h); unpack2(Q1, q1l, q1h);
            float re = (p0l - q0h) + (p1l - q1h);
            float im = (p0h + q0l) + (p1h + q1l);
            re += __shfl_xor_sync(0xffffffffu, re, 1);
            im += __shfl_xor_sync(0xffffffffu, im, 1);
            re += __shfl_xor_sync(0xffffffffu, re, 2);
            im += __shfl_xor_sync(0xffffffffu, im, 2);
            re += __shfl_xor_sync(0xffffffffu, re, 4);
            im += __shfl_xor_sync(0xffffffffu, im, 4);
            if (sg == 0) xnxt[i] = make_float2(re, im);
        }
        __syncthreads();
        float2* tmp = xcur; xcur = xnxt; xnxt = tmp;
    }
}

// ---------------------------------------------------------------------------

static const int SSM_SMEM =
    (64 * PAD + 32 * PAD + 2 * 64 + 2 * 64 + 2 * 64 + 64) * (int)sizeof(float2);

extern "C" void kernel_launch(void* const* d_in, const int* in_sizes, int n_in,
                              void* d_out, int out_size) {
    (void)in_sizes; (void)n_in; (void)out_size;
    const float* A     = (const float*)d_in[0];
    const float* B     = (const float*)d_in[1];
    const float* C     = (const float*)d_in[2];
    const float* logdt = (const float*)d_in[3];

    cudaFuncSetAttribute(ssm_kernel, cudaFuncAttributeMaxDynamicSharedMemorySize,
                         SSM_SMEM);
    ssm_kernel<<<HH, TT, SSM_SMEM>>>(A, B, C, logdt, (float*)d_out);
}